// round 6
// baseline (speedup 1.0000x reference)
#include <cuda_runtime.h>
#include <cuda_fp16.h>
#include <math.h>
#include <stdint.h>

// Problem constants
#define B_    512
#define N_    64
#define H_    256
#define BN_   32768          // B_*N_
#define KX    768            // X = [inp(512) | h(256)]
#define NG    1024           // G columns: [r-sum | i-sum | i_n | h_n]

// ---------------- device scratch (static, allocation-free) ----------------
__device__ __half g_X[(size_t)BN_ * KX];        // fp16 activations [32768,768]
__device__ __half g_hcat[(size_t)BN_ * 512];    // fp16 [32768,512] = [hin | hout]
__device__ __half g_Wpack[NG * KX];             // packed big weight [1024,768] fp16
__device__ float  g_bpack[NG];
__device__ __half g_Wcat[512 * H_];             // [W_in; W_out] rows fp16
__device__ float  g_bcat[512];

// ---------------- K0: pack weights/biases (fp16 weights) ----------
__global__ void build_pack(const float* __restrict__ w_ih, const float* __restrict__ w_hh,
                           const float* __restrict__ b_ih, const float* __restrict__ b_hh,
                           const float* __restrict__ W_in, const float* __restrict__ b_in,
                           const float* __restrict__ W_out, const float* __restrict__ b_out)
{
    const int stride = gridDim.x * blockDim.x;
    const int idx = blockIdx.x * blockDim.x + threadIdx.x;

    for (int i = idx; i < NG * KX; i += stride) {
        int n = i / KX, k = i - n * KX;
        float v = 0.f;
        if (n < 512)      v = (k < 512) ? w_ih[n * 512 + k] : w_hh[n * 256 + (k - 512)];
        else if (n < 768) v = (k < 512) ? w_ih[n * 512 + k] : 0.f;
        else              v = (k >= 512) ? w_hh[(n - 256) * 256 + (k - 512)] : 0.f;
        g_Wpack[i] = __float2half_rn(v);
    }
    for (int i = idx; i < 512 * H_; i += stride) {
        float v = (i < 256 * H_) ? W_in[i] : W_out[i - 256 * H_];
        g_Wcat[i] = __float2half_rn(v);
    }
    for (int i = idx; i < NG; i += stride) {
        float bv;
        if (i < 512)      bv = b_ih[i] + b_hh[i];
        else if (i < 768) bv = b_ih[i];
        else              bv = b_hh[i - 256];
        g_bpack[i] = bv;
    }
    for (int i = idx; i < 512; i += stride)
        g_bcat[i] = (i < 256) ? b_in[i] : b_out[i - 256];
}

// ---------------- K1: gather + L2 normalize (warp per row) ----------
__global__ void __launch_bounds__(256) gather_norm(const int* __restrict__ inputs,
                                                   const float* __restrict__ emb)
{
    const int row = blockIdx.x * 8 + (threadIdx.x >> 5);
    const int lane = threadIdx.x & 31;
    const float4* e = (const float4*)(emb + (size_t)inputs[row] * H_) + lane * 2;
    float4 v0 = e[0], v1 = e[1];
    float ss = v0.x * v0.x + v0.y * v0.y + v0.z * v0.z + v0.w * v0.w
             + v1.x * v1.x + v1.y * v1.y + v1.z * v1.z + v1.w * v1.w;
    #pragma unroll
    for (int o = 16; o > 0; o >>= 1) ss += __shfl_xor_sync(0xffffffffu, ss, o);
    float sc = 1.f / (sqrtf(ss) + 1e-12f);
    __half2 h[4];
    h[0] = __floats2half2_rn(v0.x * sc, v0.y * sc);
    h[1] = __floats2half2_rn(v0.z * sc, v0.w * sc);
    h[2] = __floats2half2_rn(v1.x * sc, v1.y * sc);
    h[3] = __floats2half2_rn(v1.z * sc, v1.w * sc);
    *(uint4*)&g_X[(size_t)row * KX + 512 + lane * 8] = *(uint4*)h;
}

// ---------------- helpers ----------------
__device__ __forceinline__ void cp_async16(void* smem_dst, const void* gmem_src) {
    uint32_t sa = (uint32_t)__cvta_generic_to_shared(smem_dst);
    asm volatile("cp.async.cg.shared.global [%0], [%1], 16;\n" :: "r"(sa), "l"(gmem_src));
}
__device__ __forceinline__ void cp_commit() { asm volatile("cp.async.commit_group;\n"); }

__device__ __forceinline__ void ldm_x4(uint32_t& r0, uint32_t& r1, uint32_t& r2, uint32_t& r3,
                                       uint32_t addr) {
    asm volatile("ldmatrix.sync.aligned.m8n8.x4.shared.b16 {%0,%1,%2,%3}, [%4];"
                 : "=r"(r0), "=r"(r1), "=r"(r2), "=r"(r3) : "r"(addr));
}
__device__ __forceinline__ void ldm_x4_t(uint32_t& r0, uint32_t& r1, uint32_t& r2, uint32_t& r3,
                                         uint32_t addr) {
    asm volatile("ldmatrix.sync.aligned.m8n8.x4.trans.shared.b16 {%0,%1,%2,%3}, [%4];"
                 : "=r"(r0), "=r"(r1), "=r"(r2), "=r"(r3) : "r"(addr));
}
#define HMMA16816(ac, a0, a1, a2, a3, b0, b1)                                          \
    asm volatile(                                                                      \
        "mma.sync.aligned.m16n8k16.row.col.f32.f16.f16.f32 "                           \
        "{%0,%1,%2,%3}, {%4,%5,%6,%7}, {%8,%9}, {%0,%1,%2,%3};\n"                      \
        : "+f"((ac)[0]), "+f"((ac)[1]), "+f"((ac)[2]), "+f"((ac)[3])                   \
        : "r"(a0), "r"(a1), "r"(a2), "r"(a3), "r"(b0), "r"(b1))

// ---------------- FP16 GEMM (NT) for GEMM1: C = A@B^T + bias -> fp16 -----
#define SM_STRIDE 36
#define TILE_U32 (128 * SM_STRIDE)
#define STAGE_U32 (2 * TILE_U32)

__global__ void __launch_bounds__(256, 2) mma_gemm_f16(
    const __half* __restrict__ Am, int lda,
    const __half* __restrict__ Bm, int ldb,
    const float* __restrict__ bias,
    __half* __restrict__ C, int ldc, int K)
{
    extern __shared__ uint32_t sm[];
    const uint32_t smBase = (uint32_t)__cvta_generic_to_shared(sm);

    const int tid = threadIdx.x;
    const int m0 = blockIdx.x * 128;
    const int n0 = blockIdx.y * 128;

    const int lane = tid & 31;
    const int g = lane >> 2;
    const int t = lane & 3;
    const int warpId = tid >> 5;
    const int wm = (warpId >> 2) * 64;
    const int wn = (warpId & 3) * 32;

    const int ldr = tid >> 1;
    const int ldh = (tid & 1) * 32;
    const __half* gA = Am + (size_t)(m0 + ldr) * lda + ldh;
    const __half* gB = Bm + (size_t)(n0 + ldr) * ldb + ldh;
    const int sOff = ldr * SM_STRIDE + (tid & 1) * 16;

    const uint32_t aOff = (uint32_t)(((wm + (lane & 15)) * SM_STRIDE + (lane >> 4) * 4) * 4);
    const uint32_t bOff = (uint32_t)(((wn + (lane >> 4) * 8 + (lane & 7)) * SM_STRIDE
                                      + ((lane >> 3) & 1) * 4) * 4);

    float acc[4][4][4];
    #pragma unroll
    for (int i = 0; i < 4; i++)
        #pragma unroll
        for (int j = 0; j < 4; j++)
            #pragma unroll
            for (int c = 0; c < 4; c++) acc[i][j][c] = 0.f;

    {
        uint32_t* As = sm;
        uint32_t* Bs = sm + TILE_U32;
        #pragma unroll
        for (int j = 0; j < 4; j++) {
            cp_async16(As + sOff + j * 4, gA + j * 8);
            cp_async16(Bs + sOff + j * 4, gB + j * 8);
        }
        cp_commit();
    }

    int s = 0;
    for (int k0 = 0; k0 < K; k0 += 64, s ^= 1) {
        asm volatile("cp.async.wait_group 0;\n" ::: "memory");
        __syncthreads();

        const int kn = k0 + 64;
        if (kn < K) {
            uint32_t* As = sm + (s ^ 1) * STAGE_U32;
            uint32_t* Bs = As + TILE_U32;
            #pragma unroll
            for (int j = 0; j < 4; j++) {
                cp_async16(As + sOff + j * 4, gA + kn + j * 8);
                cp_async16(Bs + sOff + j * 4, gB + kn + j * 8);
            }
            cp_commit();
        }

        const uint32_t As_b = smBase + s * (STAGE_U32 * 4);
        const uint32_t Bs_b = As_b + TILE_U32 * 4;

        #pragma unroll
        for (int kk = 0; kk < 4; kk++) {
            uint32_t a[4][4];
            #pragma unroll
            for (int mt = 0; mt < 4; mt++)
                ldm_x4(a[mt][0], a[mt][1], a[mt][2], a[mt][3],
                       As_b + aOff + mt * (16 * SM_STRIDE * 4) + kk * 32);
            uint32_t b[4][2];
            ldm_x4(b[0][0], b[0][1], b[1][0], b[1][1], Bs_b + bOff + kk * 32);
            ldm_x4(b[2][0], b[2][1], b[3][0], b[3][1],
                   Bs_b + bOff + 2 * (8 * SM_STRIDE * 4) + kk * 32);

            #pragma unroll
            for (int mt = 0; mt < 4; mt++)
                #pragma unroll
                for (int nt = 0; nt < 4; nt++)
                    HMMA16816(acc[mt][nt], a[mt][0], a[mt][1], a[mt][2], a[mt][3],
                              b[nt][0], b[nt][1]);
        }
        __syncthreads();
    }

    #pragma unroll
    for (int nt = 0; nt < 4; nt++) {
        const int col = n0 + wn + nt * 8 + t * 2;
        const float b0 = bias[col], b1 = bias[col + 1];
        #pragma unroll
        for (int mt = 0; mt < 4; mt++) {
            const int row = m0 + wm + mt * 16 + g;
            *(__half2*)(C + (size_t)row * ldc + col) =
                __floats2half2_rn(acc[mt][nt][0] + b0, acc[mt][nt][1] + b1);
            *(__half2*)(C + (size_t)(row + 8) * ldc + col) =
                __floats2half2_rn(acc[mt][nt][2] + b0, acc[mt][nt][3] + b1);
        }
    }
}

// ---------------- K3: per-batch adjacency matmuls (tensor cores) ----------
#define SA_STRIDE 36
#define SH_STRIDE 68
__global__ void __launch_bounds__(256) adjacency_mma(const float* __restrict__ Aadj,
                                                     const float* __restrict__ b_iah,
                                                     const float* __restrict__ b_oah)
{
    __shared__ __align__(16) uint32_t shA[64 * SA_STRIDE];
    __shared__ __align__(16) uint32_t shH[64 * SH_STRIDE];
    const int b = blockIdx.x;
    const int tid = threadIdx.x;
    const int lane = tid & 31;
    const int wid = tid >> 5;
    const int mw = wid >> 2;
    const int nw = wid & 3;
    const int g = lane >> 2;
    const int t = lane & 3;
    const float* Ab = Aadj + (size_t)b * (64 * 128);
    const int r0 = b * 64;

    const uint32_t shA_b = (uint32_t)__cvta_generic_to_shared(shA);
    const uint32_t shH_b = (uint32_t)__cvta_generic_to_shared(shH);
    const uint32_t aOff = (uint32_t)(((mw * 32 + (lane & 15)) * SA_STRIDE + (lane >> 4) * 4) * 4);
    const uint32_t hOff = (uint32_t)(((lane & 15) * SH_STRIDE + nw * 16 + (lane >> 4) * 4) * 4);

    for (int half = 0; half < 2; half++) {
        const float* bias = half ? b_oah : b_iah;
        __syncthreads();
        for (int i = tid; i < 64 * 32; i += 256) {
            int n = i >> 5, m2 = (i & 31) * 2;
            float2 v = *(const float2*)&Ab[n * 128 + half * 64 + m2];
            *(__half2*)&shA[n * SA_STRIDE + m2 / 2] = __floats2half2_rn(v.x, v.y);
        }
        for (int chunk = 0; chunk < 2; chunk++) {
            __syncthreads();
            for (int i = tid; i < 64 * 16; i += 256) {
                int m = i >> 4, c8 = (i & 15) * 8;
                uint4 v = *(const uint4*)&g_hcat[(size_t)(r0 + m) * 512
                                                 + half * 256 + chunk * 128 + c8];
                *(uint4*)&shH[m * SH_STRIDE + c8 / 2] = v;
            }
            __syncthreads();

            float acc[2][4][4];
            #pragma unroll
            for (int i = 0; i < 2; i++)
                #pragma unroll
                for (int j = 0; j < 4; j++)
                    #pragma unroll
                    for (int c = 0; c < 4; c++) acc[i][j][c] = 0.f;

            #pragma unroll
            for (int kk = 0; kk < 4; kk++) {
                uint32_t a[2][4];
                #pragma unroll
                for (int mt = 0; mt < 2; mt++)
                    ldm_x4(a[mt][0], a[mt][1], a[mt][2], a[mt][3],
                           shA_b + aOff + mt * (16 * SA_STRIDE * 4) + kk * 32);
                uint32_t bb[4][2];
                ldm_x4_t(bb[0][0], bb[0][1], bb[1][0], bb[1][1],
                         shH_b + hOff + kk * (16 * SH_STRIDE * 4));
                ldm_x4_t(bb[2][0], bb[2][1], bb[3][0], bb[3][1],
                         shH_b + hOff + kk * (16 * SH_STRIDE * 4) + 2 * 16);
                #pragma unroll
                for (int mt = 0; mt < 2; mt++)
                    #pragma unroll
                    for (int nt = 0; nt < 4; nt++)
                        HMMA16816(acc[mt][nt], a[mt][0], a[mt][1], a[mt][2], a[mt][3],
                                  bb[nt][0], bb[nt][1]);
            }

            #pragma unroll
            for (int nt = 0; nt < 4; nt++) {
                const int c = nw * 32 + nt * 8 + t * 2;
                const int cc = chunk * 128 + c;
                const float b0 = bias[cc], b1 = bias[cc + 1];
                #pragma unroll
                for (int mt = 0; mt < 2; mt++) {
                    const int n = mw * 32 + mt * 16 + g;
                    __half* dst = g_X + (size_t)(r0 + n) * KX + half * 256 + cc;
                    *(__half2*)dst = __floats2half2_rn(acc[mt][nt][0] + b0,
                                                       acc[mt][nt][1] + b1);
                    __half* dst8 = g_X + (size_t)(r0 + n + 8) * KX + half * 256 + cc;
                    *(__half2*)dst8 = __floats2half2_rn(acc[mt][nt][2] + b0,
                                                        acc[mt][nt][3] + b1);
                }
            }
        }
    }
}

// ================= K4: fused GEMM2 + gates -> out ======================
// CTA: 128 rows x 64 H-cols. B tile = 256 Wpack rows {c, 256+c, 512+c, 768+c}.
// Unified K loop 0..768 with group skipping. Gates computed in registers.
#define FG_STG_U32 ((128 + 256) * SM_STRIDE)        // 13824 u32 per stage
#define FG_SMEM (3 * FG_STG_U32 * 4)                // 165888 bytes

__global__ void __launch_bounds__(256) gemm2_gates(const float* __restrict__ bias,
                                                   float* __restrict__ out)
{
    extern __shared__ uint32_t sm[];
    const uint32_t smBase = (uint32_t)__cvta_generic_to_shared(sm);

    const int tid = threadIdx.x;
    const int lane = tid & 31;
    const int wid = tid >> 5;
    const int mw = wid >> 2;          // 0..1
    const int nw = wid & 3;           // 0..3
    const int g = lane >> 2;
    const int t = lane & 3;
    const int m0 = blockIdx.x * 128;
    const int c0 = blockIdx.y * 64;

    // load addressing
    const int ldr = tid >> 1;                 // 0..127
    const int ldh = (tid & 1) * 32;           // halves
    const int sOffA = ldr * SM_STRIDE + (tid & 1) * 16;
    const __half* gA = g_X + (size_t)(m0 + ldr) * KX + ldh;
    // B rows: rr in [0,256): wrow = (rr>>6)*256 + c0 + (rr&63)
    int rrA = ldr, rrB = 128 + ldr;
    const __half* gB0 = g_Wpack + (size_t)((rrA >> 6) * 256 + c0 + (rrA & 63)) * KX + ldh;
    const __half* gB1 = g_Wpack + (size_t)((rrB >> 6) * 256 + c0 + (rrB & 63)) * KX + ldh;
    const int sOffB0 = rrA * SM_STRIDE + (tid & 1) * 16;
    const int sOffB1 = rrB * SM_STRIDE + (tid & 1) * 16;

    // ldmatrix addressing
    const uint32_t aOff = (uint32_t)(((mw * 64 + (lane & 15)) * SM_STRIDE + (lane >> 4) * 4) * 4);
    const uint32_t bOff = (uint32_t)(((nw * 16 + (lane >> 4) * 8 + (lane & 7)) * SM_STRIDE
                                      + ((lane >> 3) & 1) * 4) * 4);

    float acc[4][8][4];
    #pragma unroll
    for (int i = 0; i < 4; i++)
        #pragma unroll
        for (int j = 0; j < 8; j++)
            #pragma unroll
            for (int c = 0; c < 4; c++) acc[i][j][c] = 0.f;

    // stage loader
    auto load_stage = [&](int slot, int k0) {
        uint32_t* As = sm + slot * FG_STG_U32;
        uint32_t* Bs = As + 128 * SM_STRIDE;
        #pragma unroll
        for (int j = 0; j < 4; j++)
            cp_async16(As + sOffA + j * 4, gA + k0 + j * 8);
        #pragma unroll
        for (int j = 0; j < 4; j++)
            cp_async16(Bs + sOffB0 + j * 4, gB0 + k0 + j * 8);
        #pragma unroll
        for (int j = 0; j < 4; j++)
            cp_async16(Bs + sOffB1 + j * 4, gB1 + k0 + j * 8);
        cp_commit();
    };

    const int T = KX / 64;   // 12
    load_stage(0, 0);
    load_stage(1, 64);

    for (int kt = 0; kt < T; kt++) {
        if (kt + 2 < T)
            asm volatile("cp.async.wait_group 1;\n" ::: "memory");
        else
            asm volatile("cp.async.wait_group 0;\n" ::: "memory");
        __syncthreads();

        if (kt + 2 < T)
            load_stage((kt + 2) % 3, (kt + 2) * 64);

        const int slot = kt % 3;
        const int k0 = kt * 64;
        const int g2 = (k0 < 512) ? 2 : 3;
        const uint32_t As_b = smBase + slot * (FG_STG_U32 * 4);
        const uint32_t Bs_b = As_b + 128 * SM_STRIDE * 4;
        const uint32_t bOff2 = bOff + (uint32_t)(g2 * 64 * SM_STRIDE * 4);

        #pragma unroll
        for (int kk = 0; kk < 4; kk++) {
            uint32_t a[4][4];
            #pragma unroll
            for (int mt = 0; mt < 4; mt++)
                ldm_x4(a[mt][0], a[mt][1], a[mt][2], a[mt][3],
                       As_b + aOff + mt * (16 * SM_STRIDE * 4) + kk * 32);
            uint32_t b0[4], b1[4], b2[4];
            ldm_x4(b0[0], b0[1], b0[2], b0[3], Bs_b + bOff + kk * 32);
            ldm_x4(b1[0], b1[1], b1[2], b1[3],
                   Bs_b + bOff + (64 * SM_STRIDE * 4) + kk * 32);
            ldm_x4(b2[0], b2[1], b2[2], b2[3], Bs_b + bOff2 + kk * 32);

            #pragma unroll
            for (int mt = 0; mt < 4; mt++) {
                HMMA16816(acc[mt][0], a[mt][0], a[mt][1], a[mt][2], a[mt][3], b0[0], b0[1]);
                HMMA16816(acc[mt][1], a[mt][0], a[mt][1], a[mt][2], a[mt][3], b0[2], b0[3]);
                HMMA16816(acc[mt][2], a[mt][0], a[mt][1], a[mt][2], a[mt][3], b1[0], b1[1]);
                HMMA16816(acc[mt][3], a[mt][0], a[mt][1], a[mt][2], a[mt][3], b1[2], b1[3]);
                if (g2 == 2) {
                    HMMA16816(acc[mt][4], a[mt][0], a[mt][1], a[mt][2], a[mt][3], b2[0], b2[1]);
                    HMMA16816(acc[mt][5], a[mt][0], a[mt][1], a[mt][2], a[mt][3], b2[2], b2[3]);
                } else {
                    HMMA16816(acc[mt][6], a[mt][0], a[mt][1], a[mt][2], a[mt][3], b2[0], b2[1]);
                    HMMA16816(acc[mt][7], a[mt][0], a[mt][1], a[mt][2], a[mt][3], b2[2], b2[3]);
                }
            }
        }
        __syncthreads();
    }

    // ---- gates epilogue, in registers ----
    #pragma unroll
    for (int s = 0; s < 2; s++) {
        const int col = c0 + nw * 16 + s * 8 + t * 2;
        const float bR0 = bias[col],       bR1 = bias[col + 1];
        const float bI0 = bias[256 + col], bI1 = bias[256 + col + 1];
        const float bN0 = bias[512 + col], bN1 = bias[512 + col + 1];
        const float bH0 = bias[768 + col], bH1 = bias[768 + col + 1];
        #pragma unroll
        for (int mt = 0; mt < 4; mt++) {
            #pragma unroll
            for (int hf = 0; hf < 2; hf++) {
                const int row = m0 + mw * 64 + mt * 16 + g + hf * 8;
                float sr0 = acc[mt][0 + s][hf * 2 + 0] + bR0;
                float sr1 = acc[mt][0 + s][hf * 2 + 1] + bR1;
                float si0 = acc[mt][2 + s][hf * 2 + 0] + bI0;
                float si1 = acc[mt][2 + s][hf * 2 + 1] + bI1;
                float vn0 = acc[mt][4 + s][hf * 2 + 0] + bN0;
                float vn1 = acc[mt][4 + s][hf * 2 + 1] + bN1;
                float vh0 = acc[mt][6 + s][hf * 2 + 0] + bH0;
                float vh1 = acc[mt][6 + s][hf * 2 + 1] + bH1;
                __half2 hv = *(const __half2*)&g_X[(size_t)row * KX + 512 + col];
                float hx = __low2float(hv), hy = __high2float(hv);
                float rg0 = 1.f / (1.f + expf(-sr0)), rg1 = 1.f / (1.f + expf(-sr1));
                float ig0 = 1.f / (1.f + expf(-si0)), ig1 = 1.f / (1.f + expf(-si1));
                float ng0 = tanhf(vn0 + rg0 * vh0), ng1 = tanhf(vn1 + rg1 * vh1);
                float2 o;
                o.x = ng0 + ig0 * (hx - ng0);
                o.y = ng1 + ig1 * (hy - ng1);
                *(float2*)&out[(size_t)row * H_ + col] = o;
            }
        }
    }
}

// ---------------- launcher ----------------
extern "C" void kernel_launch(void* const* d_in, const int* in_sizes, int n_in,
                              void* d_out, int out_size)
{
    const int*   inputs = (const int*)  d_in[0];   // [512,64]
    const float* Aadj   = (const float*)d_in[1];   // [512,64,128]
    const float* emb    = (const float*)d_in[2];   // [100000,256]
    const float* W_in   = (const float*)d_in[3];
    const float* b_in   = (const float*)d_in[4];
    const float* W_out  = (const float*)d_in[5];
    const float* b_out  = (const float*)d_in[6];
    const float* w_ih   = (const float*)d_in[7];   // [768,512]
    const float* b_ih   = (const float*)d_in[8];
    const float* w_hh   = (const float*)d_in[9];   // [768,256]
    const float* b_hh   = (const float*)d_in[10];
    const float* b_iah  = (const float*)d_in[11];
    const float* b_oah  = (const float*)d_in[12];
    float* out = (float*)d_out;

    __half *d_X, *d_Wcat, *d_hcat;
    float *d_bpack, *d_bcat;
    cudaGetSymbolAddress((void**)&d_X, g_X);
    cudaGetSymbolAddress((void**)&d_hcat, g_hcat);
    cudaGetSymbolAddress((void**)&d_bpack, g_bpack);
    cudaGetSymbolAddress((void**)&d_Wcat, g_Wcat);
    cudaGetSymbolAddress((void**)&d_bcat, g_bcat);

    static int smem_set = 0;
    if (!smem_set) {
        cudaFuncSetAttribute(mma_gemm_f16,
                             cudaFuncAttributeMaxDynamicSharedMemorySize,
                             2 * STAGE_U32 * (int)sizeof(uint32_t));
        cudaFuncSetAttribute(gemm2_gates,
                             cudaFuncAttributeMaxDynamicSharedMemorySize, FG_SMEM);
        smem_set = 1;
    }
    const int smemBytes = 2 * STAGE_U32 * (int)sizeof(uint32_t);  // 73728

    // K0: pack weights (fp16)
    build_pack<<<512, 256>>>(w_ih, w_hh, b_ih, b_hh, W_in, b_in, W_out, b_out);

    // K1: gather + normalize into X[:,512:768] (fp16, warp per row)
    gather_norm<<<BN_ / 8, 256>>>(inputs, emb);

    // K2: hcat = h @ Wcat^T + bcat   (M=32768, N=512, K=256) — fp16 HMMA
    mma_gemm_f16<<<dim3(BN_ / 128, 512 / 128), 256, smemBytes>>>(
        d_X + 512, KX, d_Wcat, H_, d_bcat, d_hcat, 512, 256);

    // K3: adjacency -> X[:,0:512] — fp16 HMMA
    adjacency_mma<<<B_, 256>>>(Aadj, b_iah, b_oah);

    // K4: fused GEMM2 + gates -> out
    gemm2_gates<<<dim3(BN_ / 128, H_ / 64), 256, FG_SMEM>>>(d_bpack, out);
}

// round 8
// speedup vs baseline: 1.5006x; 1.5006x over previous
#include <cuda_runtime.h>
#include <cuda_fp16.h>
#include <math.h>
#include <stdint.h>

// Problem constants
#define B_    512
#define N_    64
#define H_    256
#define BN_   32768          // B_*N_
#define KX    768            // X = [inp(512) | h(256)]
#define NG    1024           // G columns: [r-sum | i-sum | i_n | h_n]

// ---------------- device scratch (static, allocation-free) ----------------
__device__ __half g_X[(size_t)BN_ * KX];        // fp16 activations [32768,768]
__device__ __half g_hcat[(size_t)BN_ * 512];    // fp16 [32768,512] = [hin | hout]
__device__ __half g_G[(size_t)BN_ * NG];        // fp16 [32768,1024]
__device__ __half g_Wpack[NG * KX];             // packed big weight [1024,768] fp16
__device__ float  g_bpack[NG];
__device__ __half g_Wcat[512 * H_];             // [W_in; W_out] rows fp16
__device__ float  g_bcat[512];

// ---------------- K0: pack weights/biases (fp16 weights) ----------
__global__ void build_pack(const float* __restrict__ w_ih, const float* __restrict__ w_hh,
                           const float* __restrict__ b_ih, const float* __restrict__ b_hh,
                           const float* __restrict__ W_in, const float* __restrict__ b_in,
                           const float* __restrict__ W_out, const float* __restrict__ b_out)
{
    const int stride = gridDim.x * blockDim.x;
    const int idx = blockIdx.x * blockDim.x + threadIdx.x;

    for (int i = idx; i < NG * KX; i += stride) {
        int n = i / KX, k = i - n * KX;
        float v = 0.f;
        if (n < 512)      v = (k < 512) ? w_ih[n * 512 + k] : w_hh[n * 256 + (k - 512)];
        else if (n < 768) v = (k < 512) ? w_ih[n * 512 + k] : 0.f;
        else              v = (k >= 512) ? w_hh[(n - 256) * 256 + (k - 512)] : 0.f;
        g_Wpack[i] = __float2half_rn(v);
    }
    for (int i = idx; i < 512 * H_; i += stride) {
        float v = (i < 256 * H_) ? W_in[i] : W_out[i - 256 * H_];
        g_Wcat[i] = __float2half_rn(v);
    }
    for (int i = idx; i < NG; i += stride) {
        float bv;
        if (i < 512)      bv = b_ih[i] + b_hh[i];
        else if (i < 768) bv = b_ih[i];
        else              bv = b_hh[i - 256];
        g_bpack[i] = bv;
    }
    for (int i = idx; i < 512; i += stride)
        g_bcat[i] = (i < 256) ? b_in[i] : b_out[i - 256];
}

// ---------------- K1: gather + L2 normalize (warp per row) ----------
__global__ void __launch_bounds__(256) gather_norm(const int* __restrict__ inputs,
                                                   const float* __restrict__ emb)
{
    const int row = blockIdx.x * 8 + (threadIdx.x >> 5);
    const int lane = threadIdx.x & 31;
    const float4* e = (const float4*)(emb + (size_t)inputs[row] * H_) + lane * 2;
    float4 v0 = e[0], v1 = e[1];
    float ss = v0.x * v0.x + v0.y * v0.y + v0.z * v0.z + v0.w * v0.w
             + v1.x * v1.x + v1.y * v1.y + v1.z * v1.z + v1.w * v1.w;
    #pragma unroll
    for (int o = 16; o > 0; o >>= 1) ss += __shfl_xor_sync(0xffffffffu, ss, o);
    float sc = 1.f / (sqrtf(ss) + 1e-12f);
    __half2 h[4];
    h[0] = __floats2half2_rn(v0.x * sc, v0.y * sc);
    h[1] = __floats2half2_rn(v0.z * sc, v0.w * sc);
    h[2] = __floats2half2_rn(v1.x * sc, v1.y * sc);
    h[3] = __floats2half2_rn(v1.z * sc, v1.w * sc);
    *(uint4*)&g_X[(size_t)row * KX + 512 + lane * 8] = *(uint4*)h;
}

// ---------------- helpers ----------------
__device__ __forceinline__ void cp_async16(void* smem_dst, const void* gmem_src) {
    uint32_t sa = (uint32_t)__cvta_generic_to_shared(smem_dst);
    asm volatile("cp.async.cg.shared.global [%0], [%1], 16;\n" :: "r"(sa), "l"(gmem_src));
}
__device__ __forceinline__ void cp_commit() { asm volatile("cp.async.commit_group;\n"); }

__device__ __forceinline__ void ldm_x4(uint32_t& r0, uint32_t& r1, uint32_t& r2, uint32_t& r3,
                                       uint32_t addr) {
    asm volatile("ldmatrix.sync.aligned.m8n8.x4.shared.b16 {%0,%1,%2,%3}, [%4];"
                 : "=r"(r0), "=r"(r1), "=r"(r2), "=r"(r3) : "r"(addr));
}
__device__ __forceinline__ void ldm_x4_t(uint32_t& r0, uint32_t& r1, uint32_t& r2, uint32_t& r3,
                                         uint32_t addr) {
    asm volatile("ldmatrix.sync.aligned.m8n8.x4.trans.shared.b16 {%0,%1,%2,%3}, [%4];"
                 : "=r"(r0), "=r"(r1), "=r"(r2), "=r"(r3) : "r"(addr));
}
#define HMMA16816(ac, a0, a1, a2, a3, b0, b1)                                          \
    asm volatile(                                                                      \
        "mma.sync.aligned.m16n8k16.row.col.f32.f16.f16.f32 "                           \
        "{%0,%1,%2,%3}, {%4,%5,%6,%7}, {%8,%9}, {%0,%1,%2,%3};\n"                      \
        : "+f"((ac)[0]), "+f"((ac)[1]), "+f"((ac)[2]), "+f"((ac)[3])                   \
        : "r"(a0), "r"(a1), "r"(a2), "r"(a3), "r"(b0), "r"(b1))

// ---------------- FP16 tensor-core GEMM (NT), 4-stage cp.async pipeline ----
// CTA tile 128x128, BK=32 halves/stage, 4 stages, 256 threads (8 warps),
// warp tile 64x32 (4x4 of m16n8k16).
// Row stride: 16 data u32 + 4 pad = 20 u32 (80 B, 16B-aligned rows,
// ldmatrix conflict-free: row pitch = 20 banks).
#define ST_STRIDE 20                     // u32 per smem row
#define ST_TILE_U32 (128 * ST_STRIDE)    // 2560 u32 per tile
#define ST_STAGE_U32 (2 * ST_TILE_U32)   // A + B per stage (5120 u32)
#define GM_SMEM (4 * ST_STAGE_U32 * 4)   // 81920 bytes

__global__ void __launch_bounds__(256, 2) mma_gemm_f16(
    const __half* __restrict__ Am, int lda,
    const __half* __restrict__ Bm, int ldb,
    const float* __restrict__ bias,
    __half* __restrict__ C, int ldc,
    int kBegin, int kEnd, int grouped)
{
    extern __shared__ uint32_t sm[];
    const uint32_t smBase = (uint32_t)__cvta_generic_to_shared(sm);

    const int tid = threadIdx.x;
    const int m0 = blockIdx.x * 128;
    const int n0 = blockIdx.y * 128;

    int kb = kBegin, ke = kEnd;
    if (grouped) {
        if (n0 >= 768)      { kb = 512; ke = 768; }   // h_n : K over h part
        else if (n0 >= 512) { kb = 0;   ke = 512; }   // i_n : K over inp part
        else                { kb = 0;   ke = 768; }   // r/i sums : full K
    }
    const int T = (ke - kb) >> 5;    // stages of 32 halves (>= 8 always)

    const int lane = tid & 31;
    const int g = lane >> 2;
    const int t = lane & 3;
    const int warpId = tid >> 5;
    const int wm = (warpId >> 2) * 64;
    const int wn = (warpId & 3) * 32;

    // loader mapping: 512 chunks/tile, 2 per thread: chunk c -> row c>>2, col c&3
    const int ldRow0 = tid >> 2;             // chunks 0..255
    const int ldCol0 = (tid & 3);
    const int ldRow1 = (tid + 256) >> 2;     // chunks 256..511
    const int ldCol1 = (tid + 256) & 3;

    const __half* gA = Am + (size_t)m0 * lda;
    const __half* gB = Bm + (size_t)n0 * ldb;

    // ldmatrix per-thread byte offsets within a tile
    const uint32_t aOff = (uint32_t)(((wm + (lane & 15)) * ST_STRIDE + (lane >> 4) * 4) * 4);
    const uint32_t bOff = (uint32_t)(((wn + (lane >> 4) * 8 + (lane & 7)) * ST_STRIDE
                                      + ((lane >> 3) & 1) * 4) * 4);

    float acc[4][4][4];
    #pragma unroll
    for (int i = 0; i < 4; i++)
        #pragma unroll
        for (int j = 0; j < 4; j++)
            #pragma unroll
            for (int c = 0; c < 4; c++) acc[i][j][c] = 0.f;

    auto load_stage = [&](int slot, int k0) {
        uint32_t* As = sm + slot * ST_STAGE_U32;
        uint32_t* Bs = As + ST_TILE_U32;
        cp_async16(As + ldRow0 * ST_STRIDE + ldCol0 * 4,
                   gA + (size_t)ldRow0 * lda + k0 + ldCol0 * 8);
        cp_async16(As + ldRow1 * ST_STRIDE + ldCol1 * 4,
                   gA + (size_t)ldRow1 * lda + k0 + ldCol1 * 8);
        cp_async16(Bs + ldRow0 * ST_STRIDE + ldCol0 * 4,
                   gB + (size_t)ldRow0 * ldb + k0 + ldCol0 * 8);
        cp_async16(Bs + ldRow1 * ST_STRIDE + ldCol1 * 4,
                   gB + (size_t)ldRow1 * ldb + k0 + ldCol1 * 8);
        cp_commit();
    };

    // prologue: 3 stages in flight
    load_stage(0, kb);
    load_stage(1, kb + 32);
    load_stage(2, kb + 64);

    for (int kt = 0; kt < T; kt++) {
        // wait until stage kt is resident (tail-aware immediate)
        if (kt <= T - 3)      asm volatile("cp.async.wait_group 2;\n" ::: "memory");
        else if (kt == T - 2) asm volatile("cp.async.wait_group 1;\n" ::: "memory");
        else                  asm volatile("cp.async.wait_group 0;\n" ::: "memory");
        __syncthreads();

        if (kt + 3 < T)
            load_stage((kt + 3) & 3, kb + (kt + 3) * 32);

        const uint32_t As_b = smBase + (uint32_t)((kt & 3) * ST_STAGE_U32 * 4);
        const uint32_t Bs_b = As_b + ST_TILE_U32 * 4;

        #pragma unroll
        for (int kk = 0; kk < 2; kk++) {
            uint32_t a[4][4];
            #pragma unroll
            for (int mt = 0; mt < 4; mt++)
                ldm_x4(a[mt][0], a[mt][1], a[mt][2], a[mt][3],
                       As_b + aOff + mt * (16 * ST_STRIDE * 4) + kk * 32);
            uint32_t b[4][2];
            ldm_x4(b[0][0], b[0][1], b[1][0], b[1][1], Bs_b + bOff + kk * 32);
            ldm_x4(b[2][0], b[2][1], b[3][0], b[3][1],
                   Bs_b + bOff + 2 * (8 * ST_STRIDE * 4) + kk * 32);

            #pragma unroll
            for (int mt = 0; mt < 4; mt++)
                #pragma unroll
                for (int nt = 0; nt < 4; nt++)
                    HMMA16816(acc[mt][nt], a[mt][0], a[mt][1], a[mt][2], a[mt][3],
                              b[nt][0], b[nt][1]);
        }
        __syncthreads();
    }

    // epilogue: bias add + fp16 store
    #pragma unroll
    for (int nt = 0; nt < 4; nt++) {
        const int col = n0 + wn + nt * 8 + t * 2;
        const float b0 = bias[col], b1 = bias[col + 1];
        #pragma unroll
        for (int mt = 0; mt < 4; mt++) {
            const int row = m0 + wm + mt * 16 + g;
            *(__half2*)(C + (size_t)row * ldc + col) =
                __floats2half2_rn(acc[mt][nt][0] + b0, acc[mt][nt][1] + b1);
            *(__half2*)(C + (size_t)(row + 8) * ldc + col) =
                __floats2half2_rn(acc[mt][nt][2] + b0, acc[mt][nt][3] + b1);
        }
    }
}

// ---------------- K3: per-batch adjacency matmuls (tensor cores) ----------
#define SA_STRIDE 36
#define SH_STRIDE 68
__global__ void __launch_bounds__(256) adjacency_mma(const float* __restrict__ Aadj,
                                                     const float* __restrict__ b_iah,
                                                     const float* __restrict__ b_oah)
{
    __shared__ __align__(16) uint32_t shA[64 * SA_STRIDE];
    __shared__ __align__(16) uint32_t shH[64 * SH_STRIDE];
    const int b = blockIdx.x;
    const int tid = threadIdx.x;
    const int lane = tid & 31;
    const int wid = tid >> 5;
    const int mw = wid >> 2;
    const int nw = wid & 3;
    const int g = lane >> 2;
    const int t = lane & 3;
    const float* Ab = Aadj + (size_t)b * (64 * 128);
    const int r0 = b * 64;

    const uint32_t shA_b = (uint32_t)__cvta_generic_to_shared(shA);
    const uint32_t shH_b = (uint32_t)__cvta_generic_to_shared(shH);
    const uint32_t aOff = (uint32_t)(((mw * 32 + (lane & 15)) * SA_STRIDE + (lane >> 4) * 4) * 4);
    const uint32_t hOff = (uint32_t)(((lane & 15) * SH_STRIDE + nw * 16 + (lane >> 4) * 4) * 4);

    for (int half = 0; half < 2; half++) {
        const float* bias = half ? b_oah : b_iah;
        __syncthreads();
        for (int i = tid; i < 64 * 32; i += 256) {
            int n = i >> 5, m2 = (i & 31) * 2;
            float2 v = *(const float2*)&Ab[n * 128 + half * 64 + m2];
            *(__half2*)&shA[n * SA_STRIDE + m2 / 2] = __floats2half2_rn(v.x, v.y);
        }
        for (int chunk = 0; chunk < 2; chunk++) {
            __syncthreads();
            for (int i = tid; i < 64 * 16; i += 256) {
                int m = i >> 4, c8 = (i & 15) * 8;
                uint4 v = *(const uint4*)&g_hcat[(size_t)(r0 + m) * 512
                                                 + half * 256 + chunk * 128 + c8];
                *(uint4*)&shH[m * SH_STRIDE + c8 / 2] = v;
            }
            __syncthreads();

            float acc[2][4][4];
            #pragma unroll
            for (int i = 0; i < 2; i++)
                #pragma unroll
                for (int j = 0; j < 4; j++)
                    #pragma unroll
                    for (int c = 0; c < 4; c++) acc[i][j][c] = 0.f;

            #pragma unroll
            for (int kk = 0; kk < 4; kk++) {
                uint32_t a[2][4];
                #pragma unroll
                for (int mt = 0; mt < 2; mt++)
                    ldm_x4(a[mt][0], a[mt][1], a[mt][2], a[mt][3],
                           shA_b + aOff + mt * (16 * SA_STRIDE * 4) + kk * 32);
                uint32_t bb[4][2];
                ldm_x4_t(bb[0][0], bb[0][1], bb[1][0], bb[1][1],
                         shH_b + hOff + kk * (16 * SH_STRIDE * 4));
                ldm_x4_t(bb[2][0], bb[2][1], bb[3][0], bb[3][1],
                         shH_b + hOff + kk * (16 * SH_STRIDE * 4) + 2 * 16);
                #pragma unroll
                for (int mt = 0; mt < 2; mt++)
                    #pragma unroll
                    for (int nt = 0; nt < 4; nt++)
                        HMMA16816(acc[mt][nt], a[mt][0], a[mt][1], a[mt][2], a[mt][3],
                                  bb[nt][0], bb[nt][1]);
            }

            #pragma unroll
            for (int nt = 0; nt < 4; nt++) {
                const int c = nw * 32 + nt * 8 + t * 2;
                const int cc = chunk * 128 + c;
                const float b0 = bias[cc], b1 = bias[cc + 1];
                #pragma unroll
                for (int mt = 0; mt < 2; mt++) {
                    const int n = mw * 32 + mt * 16 + g;
                    __half* dst = g_X + (size_t)(r0 + n) * KX + half * 256 + cc;
                    *(__half2*)dst = __floats2half2_rn(acc[mt][nt][0] + b0,
                                                       acc[mt][nt][1] + b1);
                    __half* dst8 = g_X + (size_t)(r0 + n + 8) * KX + half * 256 + cc;
                    *(__half2*)dst8 = __floats2half2_rn(acc[mt][nt][2] + b0,
                                                        acc[mt][nt][3] + b1);
                }
            }
        }
    }
}

// ---------------- K5: gates epilogue -> out (8 cols/thread) ----------------
__global__ void __launch_bounds__(256) gates_kernel(float* __restrict__ out)
{
    int idx = blockIdx.x * blockDim.x + threadIdx.x;   // over BN_*32
    if (idx >= BN_ * 32) return;
    int r = idx >> 5;
    int c = (idx & 31) << 3;
    const __half* Gr = g_G + (size_t)r * NG;
    uint4 vr = *(const uint4*)&Gr[c];
    uint4 vi = *(const uint4*)&Gr[256 + c];
    uint4 vn = *(const uint4*)&Gr[512 + c];
    uint4 vh = *(const uint4*)&Gr[768 + c];
    uint4 vx = *(const uint4*)&g_X[(size_t)r * KX + 512 + c];
    const __half2* pr = (const __half2*)&vr;
    const __half2* pi = (const __half2*)&vi;
    const __half2* pn = (const __half2*)&vn;
    const __half2* ph = (const __half2*)&vh;
    const __half2* px = (const __half2*)&vx;

    float o[8];
    #pragma unroll
    for (int j = 0; j < 4; j++) {
        float2 sr = __half22float2(pr[j]);
        float2 si = __half22float2(pi[j]);
        float2 nn = __half22float2(pn[j]);
        float2 hh = __half22float2(ph[j]);
        float2 xx = __half22float2(px[j]);
        float rg0 = 1.f / (1.f + expf(-sr.x)), rg1 = 1.f / (1.f + expf(-sr.y));
        float ig0 = 1.f / (1.f + expf(-si.x)), ig1 = 1.f / (1.f + expf(-si.y));
        float ng0 = tanhf(nn.x + rg0 * hh.x), ng1 = tanhf(nn.y + rg1 * hh.y);
        o[j * 2 + 0] = ng0 + ig0 * (xx.x - ng0);
        o[j * 2 + 1] = ng1 + ig1 * (xx.y - ng1);
    }
    float* dst = out + (size_t)r * H_ + c;
    *(float4*)dst = *(float4*)&o[0];
    *(float4*)(dst + 4) = *(float4*)&o[4];
}

// ---------------- launcher ----------------
extern "C" void kernel_launch(void* const* d_in, const int* in_sizes, int n_in,
                              void* d_out, int out_size)
{
    const int*   inputs = (const int*)  d_in[0];   // [512,64]
    const float* Aadj   = (const float*)d_in[1];   // [512,64,128]
    const float* emb    = (const float*)d_in[2];   // [100000,256]
    const float* W_in   = (const float*)d_in[3];
    const float* b_in   = (const float*)d_in[4];
    const float* W_out  = (const float*)d_in[5];
    const float* b_out  = (const float*)d_in[6];
    const float* w_ih   = (const float*)d_in[7];   // [768,512]
    const float* b_ih   = (const float*)d_in[8];
    const float* w_hh   = (const float*)d_in[9];   // [768,256]
    const float* b_hh   = (const float*)d_in[10];
    const float* b_iah  = (const float*)d_in[11];
    const float* b_oah  = (const float*)d_in[12];
    float* out = (float*)d_out;

    __half *d_X, *d_Wpack, *d_Wcat, *d_hcat, *d_G;
    float *d_bpack, *d_bcat;
    cudaGetSymbolAddress((void**)&d_X, g_X);
    cudaGetSymbolAddress((void**)&d_hcat, g_hcat);
    cudaGetSymbolAddress((void**)&d_G, g_G);
    cudaGetSymbolAddress((void**)&d_Wpack, g_Wpack);
    cudaGetSymbolAddress((void**)&d_bpack, g_bpack);
    cudaGetSymbolAddress((void**)&d_Wcat, g_Wcat);
    cudaGetSymbolAddress((void**)&d_bcat, g_bcat);

    static int smem_set = 0;
    if (!smem_set) {
        cudaFuncSetAttribute(mma_gemm_f16,
                             cudaFuncAttributeMaxDynamicSharedMemorySize, GM_SMEM);
        smem_set = 1;
    }

    // K0: pack weights (fp16)
    build_pack<<<512, 256>>>(w_ih, w_hh, b_ih, b_hh, W_in, b_in, W_out, b_out);

    // K1: gather + normalize into X[:,512:768] (fp16, warp per row)
    gather_norm<<<BN_ / 8, 256>>>(inputs, emb);

    // K2: hcat = h @ Wcat^T + bcat   (M=32768, N=512, K=256) — fp16 HMMA
    mma_gemm_f16<<<dim3(BN_ / 128, 512 / 128), 256, GM_SMEM>>>(
        d_X + 512, KX, d_Wcat, H_, d_bcat, d_hcat, 512, 0, 256, 0);

    // K3: adjacency -> X[:,0:512] — fp16 HMMA
    adjacency_mma<<<B_, 256>>>(Aadj, b_iah, b_oah);

    // K4: G = X @ Wpack^T + bpack   (grouped K ranges) — fp16 HMMA
    mma_gemm_f16<<<dim3(BN_ / 128, NG / 128), 256, GM_SMEM>>>(
        d_X, KX, d_Wpack, KX, d_bpack, d_G, NG, 0, 0, 1);

    // K5: gates
    gates_kernel<<<(BN_ * 32 + 255) / 256, 256>>>(out);
}